// round 1
// baseline (speedup 1.0000x reference)
#include <cuda_runtime.h>
#include <math.h>

#define BB 8
#define NN 256
#define DD 128
#define ROWS (BB*NN)          // 2048
#define EROWS (BB*NN*NN)      // 524288
#define BN_EPS 1e-5f

// scratch (allocation-free rule: __device__ globals)
__device__ float g_w[EROWS];            // edge weights (B,N,N)
__device__ float g_h1[ROWS*DD];         // pre-BN activations
__device__ float g_ps[16][DD];          // partial sums
__device__ float g_pss[16][DD];         // partial sums of squares
__device__ float g_mean[DD];
__device__ float g_rstd[DD];

// ---------------------------------------------------------------------------
// Kernel 1: fused  ||e[b,i,j,:]||  +  copy e -> out_e.  One warp per edge row
// (128 floats = 32 lanes x float4). Streaming loads/stores (no L2 pollution).
// ---------------------------------------------------------------------------
__global__ void k_norm_copy(const float4* __restrict__ e,
                            float4* __restrict__ out_e,
                            float* __restrict__ w) {
    size_t warp = (size_t)((blockIdx.x * blockDim.x + threadIdx.x) >> 5);
    int lane = threadIdx.x & 31;
    if (warp >= (size_t)EROWS) return;
    size_t idx = warp * 32 + lane;
    float4 v = __ldcs(e + idx);
    __stcs(out_e + idx, v);
    float s = v.x*v.x + v.y*v.y + v.z*v.z + v.w*v.w;
    #pragma unroll
    for (int o = 16; o > 0; o >>= 1)
        s += __shfl_xor_sync(0xffffffffu, s, o);
    if (lane == 0) w[warp] = sqrtf(s);
}

// ---------------------------------------------------------------------------
// Kernel 2: softmax over source axis j (contiguous 256 per row). 1 block/row.
// ---------------------------------------------------------------------------
__global__ void k_softmax(float* __restrict__ w) {
    __shared__ float red[NN];
    int row = blockIdx.x;
    int t = threadIdx.x;
    float v = w[row * NN + t];
    red[t] = v;
    __syncthreads();
    #pragma unroll
    for (int s = NN/2; s > 0; s >>= 1) {
        if (t < s) red[t] = fmaxf(red[t], red[t + s]);
        __syncthreads();
    }
    float m = red[0];
    __syncthreads();
    float ev = __expf(v - m);
    red[t] = ev;
    __syncthreads();
    #pragma unroll
    for (int s = NN/2; s > 0; s >>= 1) {
        if (t < s) red[t] += red[t + s];
        __syncthreads();
    }
    w[row * NN + t] = ev * (1.0f / red[0]);
}

// ---------------------------------------------------------------------------
// Kernel 3: per (b,i):  x = h[b,i,:] + sum_j w[b,i,j]*h[b,j,:]
//           y = relu(x @ W^T + bias)   (einsum 'bnd,kd->bnk')
// 1 block of 128 threads per (b,i); thread t = feature index.
// ---------------------------------------------------------------------------
__global__ void k_agg_linear(const float* __restrict__ h,
                             const float* __restrict__ w,
                             const float* __restrict__ Wm,
                             const float* __restrict__ bias) {
    int bi = blockIdx.x;                 // b*NN + i
    int b  = bi >> 8;
    int i  = bi & 255;
    int t  = threadIdx.x;                // feature
    __shared__ float sw[NN];
    __shared__ float sx[DD];

    sw[t]       = w[bi * NN + t];
    sw[t + DD]  = w[bi * NN + t + DD];
    __syncthreads();

    const float* hb = h + (size_t)b * NN * DD;
    float acc = 0.0f;
    #pragma unroll 8
    for (int j = 0; j < NN; j++)
        acc = fmaf(sw[j], hb[j * DD + t], acc);

    sx[t] = hb[i * DD + t] + acc;
    __syncthreads();

    float y = bias[t];
    const float* wr = Wm + t * DD;       // W[t, :]
    #pragma unroll 8
    for (int d = 0; d < DD; d++)
        y = fmaf(sx[d], __ldg(wr + d), y);
    y = fmaxf(y, 0.0f);
    g_h1[bi * DD + t] = y;
}

// ---------------------------------------------------------------------------
// Kernel 4: BN partial stats. 16 blocks x 128 threads; block k reduces rows
// [k*128, k*128+128). Coalesced (thread t = feature t).
// ---------------------------------------------------------------------------
__global__ void k_bnstats() {
    int t = threadIdx.x;
    int blk = blockIdx.x;
    float s = 0.0f, ss = 0.0f;
    int r0 = blk * 128;
    #pragma unroll 4
    for (int r = 0; r < 128; r++) {
        float v = g_h1[(r0 + r) * DD + t];
        s  += v;
        ss = fmaf(v, v, ss);
    }
    g_ps[blk][t]  = s;
    g_pss[blk][t] = ss;
}

// Kernel 4b: finalize mean / rstd. 1 block, 128 threads.
__global__ void k_bnfinal() {
    int t = threadIdx.x;
    float s = 0.0f, ss = 0.0f;
    #pragma unroll
    for (int k = 0; k < 16; k++) { s += g_ps[k][t]; ss += g_pss[k][t]; }
    float mean = s * (1.0f / ROWS);
    float var  = ss * (1.0f / ROWS) - mean * mean;
    g_mean[t] = mean;
    g_rstd[t] = rsqrtf(var + BN_EPS);
}

// ---------------------------------------------------------------------------
// Kernel 5: normalize + affine + residual -> out_h
// ---------------------------------------------------------------------------
__global__ void k_bnapply(const float* __restrict__ h,
                          const float* __restrict__ gamma,
                          const float* __restrict__ beta,
                          float* __restrict__ out_h) {
    int t = threadIdx.x;
    float m  = g_mean[t];
    float g  = gamma[t] * g_rstd[t];
    float bt = beta[t];
    for (int row = blockIdx.x; row < ROWS; row += gridDim.x) {
        float v = g_h1[row * DD + t];
        out_h[row * DD + t] = (v - m) * g + bt + h[row * DD + t];
    }
}

// ---------------------------------------------------------------------------
extern "C" void kernel_launch(void* const* d_in, const int* in_sizes, int n_in,
                              void* d_out, int out_size) {
    const float* h     = (const float*)d_in[0];   // (8,256,128)
    const float* e     = (const float*)d_in[1];   // (8,256,256,128)
    const float* Wm    = (const float*)d_in[2];   // (128,128)
    const float* bias  = (const float*)d_in[3];   // (128)
    const float* gamma = (const float*)d_in[4];   // (128)
    const float* beta  = (const float*)d_in[5];   // (128)

    float* out_h = (float*)d_out;                 // (8,256,128) first
    float* out_e = out_h + (size_t)ROWS * DD;     // then (8,256,256,128)

    float* g_w_ptr;
    cudaGetSymbolAddress((void**)&g_w_ptr, g_w);

    // Kernel 1: 524288 warps, 8 warps/block
    k_norm_copy<<<EROWS / 8, 256>>>((const float4*)e, (float4*)out_e, g_w_ptr);
    // Kernel 2: softmax per (b,i) row
    k_softmax<<<ROWS, NN>>>(g_w_ptr);
    // Kernel 3: agg + linear + relu
    k_agg_linear<<<ROWS, DD>>>(h, g_w_ptr, Wm, bias);
    // Kernel 4: BN stats
    k_bnstats<<<16, DD>>>();
    k_bnfinal<<<1, DD>>>();
    // Kernel 5: apply BN + residual
    k_bnapply<<<256, DD>>>(h, gamma, beta, out_h);
}

// round 2
// speedup vs baseline: 1.7855x; 1.7855x over previous
#include <cuda_runtime.h>
#include <math.h>

#define BB 8
#define NN 256
#define DD 128
#define ROWS (BB*NN)          // 2048
#define EROWS (BB*NN*NN)      // 524288
#define BN_EPS 1e-5f
#define RPW 8                 // e-rows per warp in the stream kernel

// scratch (allocation-free rule: __device__ globals)
__device__ float g_w[EROWS];            // edge weights (B,N,N)
__device__ float g_h1[ROWS*DD];         // pre-BN activations
__device__ float g_sum[DD];             // BN accumulators (atomic)
__device__ float g_sumsq[DD];

// ---------------------------------------------------------------------------
// Kernel 1: fused  ||e[b,i,j,:]||  +  copy e -> out_e.
// Each warp handles RPW=8 consecutive edge rows (128 floats each).
// 8 independent float4 loads per thread (MLP_p1=8) to saturate HBM;
// 8 interleaved shuffle-reduction chains. Streaming cache hints.
// Block 0 additionally zeroes the BN atomic accumulators (stream-ordered
// before the fused kernel; deterministic across graph replays).
// ---------------------------------------------------------------------------
__global__ void k_norm_copy(const float4* __restrict__ e,
                            float4* __restrict__ out_e,
                            float* __restrict__ w) {
    if (blockIdx.x == 0 && threadIdx.x < DD) {
        g_sum[threadIdx.x]   = 0.0f;
        g_sumsq[threadIdx.x] = 0.0f;
    }
    size_t gw   = (size_t)((blockIdx.x * blockDim.x + threadIdx.x) >> 5);
    int    lane = threadIdx.x & 31;
    size_t r0   = gw * RPW;
    if (r0 >= (size_t)EROWS) return;
    size_t base = r0 * 32 + lane;

    float4 v[RPW];
    #pragma unroll
    for (int k = 0; k < RPW; k++)
        v[k] = __ldcs(e + base + (size_t)k * 32);
    #pragma unroll
    for (int k = 0; k < RPW; k++)
        __stcs(out_e + base + (size_t)k * 32, v[k]);

    float s[RPW];
    #pragma unroll
    for (int k = 0; k < RPW; k++)
        s[k] = v[k].x*v[k].x + v[k].y*v[k].y + v[k].z*v[k].z + v[k].w*v[k].w;

    #pragma unroll
    for (int o = 16; o > 0; o >>= 1) {
        #pragma unroll
        for (int k = 0; k < RPW; k++)
            s[k] += __shfl_xor_sync(0xffffffffu, s[k], o);
    }
    if (lane == 0) {
        #pragma unroll
        for (int k = 0; k < RPW; k++)
            w[r0 + k] = sqrtf(s[k]);
    }
}

// ---------------------------------------------------------------------------
// Kernel 2 (fused): per (b,i) block of 128 threads:
//   softmax over w[b,i,:]  ->  agg = sum_j p_j h[b,j,:]
//   x = h[b,i,:] + agg;  y = relu(x @ W^T + bias)
//   atomic per-feature BN partial sums.
// ---------------------------------------------------------------------------
__global__ void k_fused(const float* __restrict__ h,
                        const float* __restrict__ Wm,
                        const float* __restrict__ bias) {
    int bi = blockIdx.x;                 // b*NN + i
    int b  = bi >> 8;
    int i  = bi & 255;
    int t  = threadIdx.x;                // feature / reduction lane

    __shared__ float sw[NN];             // exp weights
    __shared__ float red[DD];
    __shared__ float sx[DD];

    const float* wrow = g_w + (size_t)bi * NN;
    float w0 = wrow[t];
    float w1 = wrow[t + DD];

    // --- max reduce over 256 values ---
    red[t] = fmaxf(w0, w1);
    __syncthreads();
    #pragma unroll
    for (int s = DD/2; s > 0; s >>= 1) {
        if (t < s) red[t] = fmaxf(red[t], red[t + s]);
        __syncthreads();
    }
    float m = red[0];
    __syncthreads();

    float e0 = __expf(w0 - m);
    float e1 = __expf(w1 - m);
    sw[t]      = e0;
    sw[t + DD] = e1;

    // --- sum reduce ---
    red[t] = e0 + e1;
    __syncthreads();
    #pragma unroll
    for (int s = DD/2; s > 0; s >>= 1) {
        if (t < s) red[t] += red[t + s];
        __syncthreads();
    }
    float inv = 1.0f / red[0];

    // --- weighted aggregation: acc = sum_j sw[j] * h[b,j,t] ---
    const float* hb = h + (size_t)b * NN * DD;
    float acc = 0.0f;
    #pragma unroll 8
    for (int j = 0; j < NN; j++)
        acc = fmaf(sw[j], hb[j * DD + t], acc);

    sx[t] = hb[i * DD + t] + acc * inv;
    __syncthreads();

    // --- linear: y_t = bias_t + sum_d sx[d] * W[t,d], relu ---
    float y = bias[t];
    const float4* wr  = (const float4*)(Wm + (size_t)t * DD);
    const float4* sx4 = (const float4*)sx;
    #pragma unroll 8
    for (int d = 0; d < DD/4; d++) {
        float4 wv = __ldg(wr + d);
        float4 xv = sx4[d];
        y = fmaf(wv.x, xv.x, y);
        y = fmaf(wv.y, xv.y, y);
        y = fmaf(wv.z, xv.z, y);
        y = fmaf(wv.w, xv.w, y);
    }
    y = fmaxf(y, 0.0f);
    g_h1[bi * DD + t] = y;

    atomicAdd(&g_sum[t],   y);
    atomicAdd(&g_sumsq[t], y * y);
}

// ---------------------------------------------------------------------------
// Kernel 3: compute mean/rstd inline (2 hot loads), normalize + affine +
// residual -> out_h.  256 blocks x 128 threads, 8 rows each.
// ---------------------------------------------------------------------------
__global__ void k_bnapply(const float* __restrict__ h,
                          const float* __restrict__ gamma,
                          const float* __restrict__ beta,
                          float* __restrict__ out_h) {
    int t = threadIdx.x;
    float s  = g_sum[t];
    float ss = g_sumsq[t];
    float mean = s * (1.0f / ROWS);
    float var  = ss * (1.0f / ROWS) - mean * mean;
    float rstd = rsqrtf(var + BN_EPS);
    float g  = gamma[t] * rstd;
    float bt = beta[t] - mean * g;
    int r0 = blockIdx.x * 8;
    #pragma unroll
    for (int k = 0; k < 8; k++) {
        int row = r0 + k;
        float v = g_h1[row * DD + t];
        out_h[row * DD + t] = fmaf(v, g, bt) + h[row * DD + t];
    }
}

// ---------------------------------------------------------------------------
extern "C" void kernel_launch(void* const* d_in, const int* in_sizes, int n_in,
                              void* d_out, int out_size) {
    const float* h     = (const float*)d_in[0];   // (8,256,128)
    const float* e     = (const float*)d_in[1];   // (8,256,256,128)
    const float* Wm    = (const float*)d_in[2];   // (128,128)
    const float* bias  = (const float*)d_in[3];   // (128)
    const float* gamma = (const float*)d_in[4];   // (128)
    const float* beta  = (const float*)d_in[5];   // (128)

    float* out_h = (float*)d_out;                 // (8,256,128) first
    float* out_e = out_h + (size_t)ROWS * DD;     // then (8,256,256,128)

    float* g_w_ptr;
    cudaGetSymbolAddress((void**)&g_w_ptr, g_w);

    // Kernel 1: 524288 rows / 8 per warp = 65536 warps / 8 warps per block
    k_norm_copy<<<EROWS / (RPW * 8), 256>>>((const float4*)e, (float4*)out_e, g_w_ptr);
    // Kernel 2: softmax + agg + linear + BN stats
    k_fused<<<ROWS, DD>>>(h, Wm, bias);
    // Kernel 3: BN apply + residual
    k_bnapply<<<ROWS / 8, DD>>>(h, gamma, beta, out_h);
}

// round 3
// speedup vs baseline: 2.0949x; 1.1733x over previous
#include <cuda_runtime.h>
#include <math.h>

#define BB 8
#define NN 256
#define DD 128
#define ROWS (BB*NN)          // 2048
#define EROWS (BB*NN*NN)      // 524288
#define BN_EPS 1e-5f
#define RPW 8                 // e-rows per warp in the stream kernel
#define TI  8                 // i-rows per block in the fused kernel

// scratch (allocation-free rule: __device__ globals)
__device__ float g_w[EROWS];            // edge weights (B,N,N)
__device__ float g_h1[ROWS*DD];         // pre-BN activations
__device__ float g_sum[DD];             // BN accumulators (atomic)
__device__ float g_sumsq[DD];

// ---------------------------------------------------------------------------
// Kernel 1: fused  ||e[b,i,j,:]||  +  copy e -> out_e.
// Each warp handles RPW=8 consecutive edge rows (128 floats each).
// 8 independent float4 loads per thread (MLP_p1=8); streaming cache hints.
// Block 0 zeroes the BN atomic accumulators (stream-ordered, replay-safe).
// Measured 6324 GB/s — at the LTS copy ceiling; do not touch.
// ---------------------------------------------------------------------------
__global__ void k_norm_copy(const float4* __restrict__ e,
                            float4* __restrict__ out_e,
                            float* __restrict__ w) {
    if (blockIdx.x == 0 && threadIdx.x < DD) {
        g_sum[threadIdx.x]   = 0.0f;
        g_sumsq[threadIdx.x] = 0.0f;
    }
    size_t gw   = (size_t)((blockIdx.x * blockDim.x + threadIdx.x) >> 5);
    int    lane = threadIdx.x & 31;
    size_t r0   = gw * RPW;
    if (r0 >= (size_t)EROWS) return;
    size_t base = r0 * 32 + lane;

    float4 v[RPW];
    #pragma unroll
    for (int k = 0; k < RPW; k++)
        v[k] = __ldcs(e + base + (size_t)k * 32);
    #pragma unroll
    for (int k = 0; k < RPW; k++)
        __stcs(out_e + base + (size_t)k * 32, v[k]);

    float s[RPW];
    #pragma unroll
    for (int k = 0; k < RPW; k++)
        s[k] = v[k].x*v[k].x + v[k].y*v[k].y + v[k].z*v[k].z + v[k].w*v[k].w;

    #pragma unroll
    for (int o = 16; o > 0; o >>= 1) {
        #pragma unroll
        for (int k = 0; k < RPW; k++)
            s[k] += __shfl_xor_sync(0xffffffffu, s[k], o);
    }
    if (lane == 0) {
        #pragma unroll
        for (int k = 0; k < RPW; k++)
            w[r0 + k] = sqrtf(s[k]);
    }
}

// ---------------------------------------------------------------------------
// Kernel 2 (fused, tiled): block of 128 threads handles TI=8 consecutive
// i-rows of one batch.
//   per row: softmax over w[b,i,:] (warp-parallel, 2 rows/warp)
//   agg[r]  = sum_j p[r][j] * h[b,j,:]   -- each h load reused 8x in regs
//   x = h[b,i_r,:] + agg[r];  y = relu(x @ W^T + bias)
//   per-thread partial BN sums -> 2 atomics/thread.
// ---------------------------------------------------------------------------
__global__ void k_fused(const float* __restrict__ h,
                        const float* __restrict__ Wm,
                        const float* __restrict__ bias) {
    int bi0 = blockIdx.x * TI;           // first (b*NN+i) row of this tile
    int b   = bi0 >> 8;
    int t   = threadIdx.x;               // feature index
    int warp = t >> 5, lane = t & 31;

    __shared__ float sw[TI][NN];         // softmax probs, 8KB
    __shared__ float sx[TI][DD];         // pre-linear activations, 4KB

    // --- softmax: each of the 4 warps owns 2 rows ---
    #pragma unroll
    for (int rr = 0; rr < 2; rr++) {
        int r = warp * 2 + rr;
        const float* wrow = g_w + (size_t)(bi0 + r) * NN;
        float v[NN/32];
        float m = -1e30f;
        #pragma unroll
        for (int k = 0; k < NN/32; k++) {
            v[k] = wrow[lane + 32*k];
            m = fmaxf(m, v[k]);
        }
        #pragma unroll
        for (int o = 16; o > 0; o >>= 1)
            m = fmaxf(m, __shfl_xor_sync(0xffffffffu, m, o));
        float sum = 0.0f;
        #pragma unroll
        for (int k = 0; k < NN/32; k++) {
            v[k] = __expf(v[k] - m);
            sum += v[k];
        }
        #pragma unroll
        for (int o = 16; o > 0; o >>= 1)
            sum += __shfl_xor_sync(0xffffffffu, sum, o);
        float inv = 1.0f / sum;
        #pragma unroll
        for (int k = 0; k < NN/32; k++)
            sw[r][lane + 32*k] = v[k] * inv;
    }
    __syncthreads();

    // --- aggregation: one global load of h[b,j,t], 8 reg-resident accs ---
    const float* hb = h + (size_t)b * NN * DD;
    float acc[TI];
    #pragma unroll
    for (int r = 0; r < TI; r++) acc[r] = 0.0f;

    #pragma unroll 4
    for (int j = 0; j < NN; j++) {
        float hv = hb[j * DD + t];
        #pragma unroll
        for (int r = 0; r < TI; r++)
            acc[r] = fmaf(sw[r][j], hv, acc[r]);
    }
    #pragma unroll
    for (int r = 0; r < TI; r++)
        sx[r][t] = hb[((bi0 & 255) + r) * DD + t] + acc[r];
    __syncthreads();

    // --- linear: y[r] = bias[t] + sum_d sx[r][d] * W[t,d]; relu ---
    float y[TI];
    float bt = bias[t];
    #pragma unroll
    for (int r = 0; r < TI; r++) y[r] = bt;

    const float4* wr = (const float4*)(Wm + (size_t)t * DD);
    #pragma unroll 4
    for (int d4 = 0; d4 < DD/4; d4++) {
        float4 wv = __ldg(wr + d4);
        #pragma unroll
        for (int r = 0; r < TI; r++) {
            const float4 xv = ((const float4*)sx[r])[d4];
            y[r] = fmaf(wv.x, xv.x, y[r]);
            y[r] = fmaf(wv.y, xv.y, y[r]);
            y[r] = fmaf(wv.z, xv.z, y[r]);
            y[r] = fmaf(wv.w, xv.w, y[r]);
        }
    }

    float ls = 0.0f, lss = 0.0f;
    #pragma unroll
    for (int r = 0; r < TI; r++) {
        float yy = fmaxf(y[r], 0.0f);
        g_h1[(bi0 + r) * DD + t] = yy;
        ls  += yy;
        lss  = fmaf(yy, yy, lss);
    }
    atomicAdd(&g_sum[t],   ls);
    atomicAdd(&g_sumsq[t], lss);
}

// ---------------------------------------------------------------------------
// Kernel 3: compute mean/rstd inline, normalize + affine + residual -> out_h
// ---------------------------------------------------------------------------
__global__ void k_bnapply(const float* __restrict__ h,
                          const float* __restrict__ gamma,
                          const float* __restrict__ beta,
                          float* __restrict__ out_h) {
    int t = threadIdx.x;
    float s  = g_sum[t];
    float ss = g_sumsq[t];
    float mean = s * (1.0f / ROWS);
    float var  = ss * (1.0f / ROWS) - mean * mean;
    float rstd = rsqrtf(var + BN_EPS);
    float g  = gamma[t] * rstd;
    float bt = beta[t] - mean * g;
    int r0 = blockIdx.x * 8;
    #pragma unroll
    for (int k = 0; k < 8; k++) {
        int row = r0 + k;
        float v = g_h1[row * DD + t];
        out_h[row * DD + t] = fmaf(v, g, bt) + h[row * DD + t];
    }
}

// ---------------------------------------------------------------------------
extern "C" void kernel_launch(void* const* d_in, const int* in_sizes, int n_in,
                              void* d_out, int out_size) {
    const float* h     = (const float*)d_in[0];   // (8,256,128)
    const float* e     = (const float*)d_in[1];   // (8,256,256,128)
    const float* Wm    = (const float*)d_in[2];   // (128,128)
    const float* bias  = (const float*)d_in[3];   // (128)
    const float* gamma = (const float*)d_in[4];   // (128)
    const float* beta  = (const float*)d_in[5];   // (128)

    float* out_h = (float*)d_out;                 // (8,256,128) first
    float* out_e = out_h + (size_t)ROWS * DD;     // then (8,256,256,128)

    float* g_w_ptr;
    cudaGetSymbolAddress((void**)&g_w_ptr, g_w);

    // Kernel 1: 524288 rows / 8 per warp, 8 warps per block
    k_norm_copy<<<EROWS / (RPW * 8), 256>>>((const float4*)e, (float4*)out_e, g_w_ptr);
    // Kernel 2: softmax + agg + linear + BN stats (8 rows per block)
    k_fused<<<ROWS / TI, DD>>>(h, Wm, bias);
    // Kernel 3: BN apply + residual
    k_bnapply<<<ROWS / 8, DD>>>(h, gamma, beta, out_h);
}

// round 4
// speedup vs baseline: 2.1657x; 1.0338x over previous
#include <cuda_runtime.h>
#include <math.h>

#define BB 8
#define NN 256
#define DD 128
#define ROWS (BB*NN)          // 2048
#define EROWS (BB*NN*NN)      // 524288
#define BN_EPS 1e-5f
#define RPW 8                 // e-rows per warp in the stream kernel
#define TI  8                 // i-rows per block in the fused kernel

// scratch (allocation-free rule: __device__ globals)
__device__ float g_w[EROWS];            // edge weights (B,N,N)
__device__ float g_h1[ROWS*DD];         // pre-BN activations
__device__ float g_sum[DD];             // BN accumulators (atomic)
__device__ float g_sumsq[DD];

// ---------------------------------------------------------------------------
// Kernel 1: fused  ||e[b,i,j,:]||  +  copy e -> out_e.
// At the measured LTS/HBM copy ceiling (6.4 TB/s) — unchanged.
// ---------------------------------------------------------------------------
__global__ void k_norm_copy(const float4* __restrict__ e,
                            float4* __restrict__ out_e,
                            float* __restrict__ w) {
    if (blockIdx.x == 0 && threadIdx.x < DD) {
        g_sum[threadIdx.x]   = 0.0f;
        g_sumsq[threadIdx.x] = 0.0f;
    }
    size_t gw   = (size_t)((blockIdx.x * blockDim.x + threadIdx.x) >> 5);
    int    lane = threadIdx.x & 31;
    size_t r0   = gw * RPW;
    if (r0 >= (size_t)EROWS) return;
    size_t base = r0 * 32 + lane;

    float4 v[RPW];
    #pragma unroll
    for (int k = 0; k < RPW; k++)
        v[k] = __ldcs(e + base + (size_t)k * 32);
    #pragma unroll
    for (int k = 0; k < RPW; k++)
        __stcs(out_e + base + (size_t)k * 32, v[k]);

    float s[RPW];
    #pragma unroll
    for (int k = 0; k < RPW; k++)
        s[k] = v[k].x*v[k].x + v[k].y*v[k].y + v[k].z*v[k].z + v[k].w*v[k].w;

    #pragma unroll
    for (int o = 16; o > 0; o >>= 1) {
        #pragma unroll
        for (int k = 0; k < RPW; k++)
            s[k] += __shfl_xor_sync(0xffffffffu, s[k], o);
    }
    if (lane == 0) {
        #pragma unroll
        for (int k = 0; k < RPW; k++)
            w[r0 + k] = sqrtf(s[k]);
    }
}

// ---------------------------------------------------------------------------
// Kernel 2 (fused, tiled): block of 128 threads handles TI=8 consecutive
// i-rows of one batch. Agg loop batches 16 independent LDGs (MLP=16) and
// reads softmax weights as float4 from smem (4x fewer LDS).
// ---------------------------------------------------------------------------
__global__ void k_fused(const float* __restrict__ h,
                        const float* __restrict__ Wm,
                        const float* __restrict__ bias) {
    int bi0 = blockIdx.x * TI;           // first (b*NN+i) row of this tile
    int b   = bi0 >> 8;
    int i0  = bi0 & 255;
    int t   = threadIdx.x;               // feature index
    int warp = t >> 5, lane = t & 31;

    __shared__ float sw[TI][NN];         // softmax probs, 8KB
    __shared__ float sx[TI][DD];         // pre-linear activations, 4KB

    // --- softmax: each of the 4 warps owns 2 rows (shuffle reductions) ---
    #pragma unroll
    for (int rr = 0; rr < 2; rr++) {
        int r = warp * 2 + rr;
        const float* wrow = g_w + (size_t)(bi0 + r) * NN;
        float v[NN/32];
        float m = -1e30f;
        #pragma unroll
        for (int k = 0; k < NN/32; k++) {
            v[k] = wrow[lane + 32*k];
            m = fmaxf(m, v[k]);
        }
        #pragma unroll
        for (int o = 16; o > 0; o >>= 1)
            m = fmaxf(m, __shfl_xor_sync(0xffffffffu, m, o));
        float sum = 0.0f;
        #pragma unroll
        for (int k = 0; k < NN/32; k++) {
            v[k] = __expf(v[k] - m);
            sum += v[k];
        }
        #pragma unroll
        for (int o = 16; o > 0; o >>= 1)
            sum += __shfl_xor_sync(0xffffffffu, sum, o);
        float inv = 1.0f / sum;
        #pragma unroll
        for (int k = 0; k < NN/32; k++)
            sw[r][lane + 32*k] = v[k] * inv;
    }
    __syncthreads();

    // --- aggregation: batch 16 independent loads, then FMA block ---
    const float* hb = h + (size_t)b * NN * DD;
    float acc[TI];
    #pragma unroll
    for (int r = 0; r < TI; r++) acc[r] = 0.0f;

    for (int j0 = 0; j0 < NN; j0 += 16) {
        float hv[16];
        #pragma unroll
        for (int k = 0; k < 16; k++)
            hv[k] = hb[(j0 + k) * DD + t];
        #pragma unroll
        for (int r = 0; r < TI; r++) {
            const float4* swr = (const float4*)&sw[r][j0];
            #pragma unroll
            for (int q = 0; q < 4; q++) {
                float4 p = swr[q];
                acc[r] = fmaf(p.x, hv[q*4+0], acc[r]);
                acc[r] = fmaf(p.y, hv[q*4+1], acc[r]);
                acc[r] = fmaf(p.z, hv[q*4+2], acc[r]);
                acc[r] = fmaf(p.w, hv[q*4+3], acc[r]);
            }
        }
    }
    #pragma unroll
    for (int r = 0; r < TI; r++)
        sx[r][t] = hb[(i0 + r) * DD + t] + acc[r];
    __syncthreads();

    // --- linear: y[r] = bias[t] + sum_d sx[r][d] * W[t,d]; relu ---
    float y[TI];
    float bt = bias[t];
    #pragma unroll
    for (int r = 0; r < TI; r++) y[r] = bt;

    const float4* wr = (const float4*)(Wm + (size_t)t * DD);
    #pragma unroll 4
    for (int d4 = 0; d4 < DD/4; d4++) {
        float4 wv = __ldg(wr + d4);
        #pragma unroll
        for (int r = 0; r < TI; r++) {
            const float4 xv = ((const float4*)sx[r])[d4];
            y[r] = fmaf(wv.x, xv.x, y[r]);
            y[r] = fmaf(wv.y, xv.y, y[r]);
            y[r] = fmaf(wv.z, xv.z, y[r]);
            y[r] = fmaf(wv.w, xv.w, y[r]);
        }
    }

    float ls = 0.0f, lss = 0.0f;
    #pragma unroll
    for (int r = 0; r < TI; r++) {
        float yy = fmaxf(y[r], 0.0f);
        g_h1[(bi0 + r) * DD + t] = yy;
        ls  += yy;
        lss  = fmaf(yy, yy, lss);
    }
    atomicAdd(&g_sum[t],   ls);
    atomicAdd(&g_sumsq[t], lss);
}

// ---------------------------------------------------------------------------
// Kernel 3: mean/rstd inline, normalize + affine + residual -> out_h.
// float4 everywhere; block=128 threads covers 4 rows (32 float4/row).
// ---------------------------------------------------------------------------
__global__ void k_bnapply(const float4* __restrict__ h,
                          const float4* __restrict__ gamma,
                          const float4* __restrict__ beta,
                          float4* __restrict__ out_h) {
    int lane = threadIdx.x & 31;         // float4 index within row
    int row  = blockIdx.x * 4 + (threadIdx.x >> 5);

    float4 s  = ((const float4*)g_sum)[lane];
    float4 ss = ((const float4*)g_sumsq)[lane];
    float4 gm = gamma[lane];
    float4 bb = beta[lane];

    const float inv = 1.0f / ROWS;
    float mx = s.x*inv, my = s.y*inv, mz = s.z*inv, mw = s.w*inv;
    float gx = gm.x * rsqrtf(ss.x*inv - mx*mx + BN_EPS);
    float gy = gm.y * rsqrtf(ss.y*inv - my*my + BN_EPS);
    float gz = gm.z * rsqrtf(ss.z*inv - mz*mz + BN_EPS);
    float gw = gm.w * rsqrtf(ss.w*inv - mw*mw + BN_EPS);
    float bx = bb.x - mx*gx, by = bb.y - my*gy, bz = bb.z - mz*gz, bw = bb.w - mw*gw;

    int idx = row * (DD/4) + lane;
    float4 v  = ((const float4*)g_h1)[idx];
    float4 hv = h[idx];
    float4 o;
    o.x = fmaf(v.x, gx, bx) + hv.x;
    o.y = fmaf(v.y, gy, by) + hv.y;
    o.z = fmaf(v.z, gz, bz) + hv.z;
    o.w = fmaf(v.w, gw, bw) + hv.w;
    out_h[idx] = o;
}

// ---------------------------------------------------------------------------
extern "C" void kernel_launch(void* const* d_in, const int* in_sizes, int n_in,
                              void* d_out, int out_size) {
    const float* h     = (const float*)d_in[0];   // (8,256,128)
    const float* e     = (const float*)d_in[1];   // (8,256,256,128)
    const float* Wm    = (const float*)d_in[2];   // (128,128)
    const float* bias  = (const float*)d_in[3];   // (128)
    const float* gamma = (const float*)d_in[4];   // (128)
    const float* beta  = (const float*)d_in[5];   // (128)

    float* out_h = (float*)d_out;                 // (8,256,128) first
    float* out_e = out_h + (size_t)ROWS * DD;     // then (8,256,256,128)

    float* g_w_ptr;
    cudaGetSymbolAddress((void**)&g_w_ptr, g_w);

    // Kernel 1: 524288 rows / 8 per warp, 8 warps per block
    k_norm_copy<<<EROWS / (RPW * 8), 256>>>((const float4*)e, (float4*)out_e, g_w_ptr);
    // Kernel 2: softmax + agg + linear + BN stats (8 rows per block)
    k_fused<<<ROWS / TI, DD>>>(h, Wm, bias);
    // Kernel 3: BN apply + residual (4 rows per block, float4)
    k_bnapply<<<ROWS / 4, DD>>>((const float4*)h, (const float4*)gamma,
                                (const float4*)beta, (float4*)out_h);
}